// round 5
// baseline (speedup 1.0000x reference)
#include <cuda_runtime.h>
#include <cstdint>

#define LN_EPS 1e-5f
#define EPS_ATTN 1e-8f
#define SCALE 0.08838834764831845f
typedef unsigned long long ull;

__device__ __forceinline__ ull fma2(ull a, ull b, ull c){ ull d; asm("fma.rn.f32x2 %0,%1,%2,%3;":"=l"(d):"l"(a),"l"(b),"l"(c)); return d; }
__device__ __forceinline__ ull add2(ull a, ull b){ ull d; asm("add.rn.f32x2 %0,%1,%2;":"=l"(d):"l"(a),"l"(b)); return d; }
__device__ __forceinline__ ull pk2(float lo, float hi){ ull d; asm("mov.b64 %0,{%1,%2};":"=l"(d):"f"(lo),"f"(hi)); return d; }
__device__ __forceinline__ void unpk(ull v, float&lo, float&hi){ asm("mov.b64 {%0,%1},%2;":"=f"(lo),"=f"(hi):"l"(v)); }
__device__ __forceinline__ float dot4(float4 a, float4 b){ return a.x*b.x+a.y*b.y+a.z*b.z+a.w*b.w; }

__device__ float g_slots[131072];
__device__ float g_slots_n[131072];
__device__ float g_qk[131072];
__device__ float g_qksum[1024];
__device__ float g_part[4194304];   // [b][tile][s][128]
__device__ float g_cs[32768];       // [b][tile][s] colsum
__device__ float g_cb[32768];       // [b][tile][s] csub

__device__ __forceinline__ float bsum(float v, volatile float* red){
    #pragma unroll
    for(int o=16;o>0;o>>=1) v += __shfl_xor_sync(0xffffffffu,v,o);
    if((threadIdx.x&31)==0) red[threadIdx.x>>5]=v;
    __syncthreads();
    v = red[0]+red[1]+red[2]+red[3];
    __syncthreads();
    return v;
}

__global__ void k_init(const float* __restrict__ noise, const float* __restrict__ mu, const float* __restrict__ ls){
    int i = blockIdx.x*blockDim.x+threadIdx.x;
    if(i<131072){ int d=i&127; g_slots[i]=mu[d]+expf(ls[d])*noise[i]; }
}

// block = batch; LN(slots) -> slots_n, q = sn@Wq.T, qk = q@Wk, qksum
__global__ void __launch_bounds__(128) k_project(const float* __restrict__ Wq, const float* __restrict__ Wk){
    __shared__ float SN[8][128], Qs[8][128], red[4];
    int b=blockIdx.x, t=threadIdx.x;
    #pragma unroll
    for(int s=0;s<8;s++){
        float v=g_slots[(b*8+s)*128+t];
        float m=bsum(v,red)*(1.f/128.f);
        float dv=v-m;
        float var=bsum(dv*dv,red)*(1.f/128.f);
        float sn=dv*rsqrtf(var+LN_EPS);
        SN[s][t]=sn; g_slots_n[(b*8+s)*128+t]=sn;
    }
    __syncthreads();
    float q[8]={0,0,0,0,0,0,0,0};
    const float4* wq=(const float4*)(Wq+(size_t)t*128);
    #pragma unroll 4
    for(int c=0;c<32;c++){ float4 w=wq[c];
        #pragma unroll
        for(int s=0;s<8;s++) q[s]+=dot4(w,((const float4*)SN[s])[c]); }
    #pragma unroll
    for(int s=0;s<8;s++) Qs[s][t]=q[s];
    __syncthreads();
    float a[8]={0,0,0,0,0,0,0,0};
    #pragma unroll 4
    for(int d=0;d<128;d++){ float wk=Wk[d*128+t];
        #pragma unroll
        for(int s=0;s<8;s++) a[s]+=Qs[s][d]*wk; }
    #pragma unroll
    for(int s=0;s<8;s++){
        g_qk[(b*8+s)*128+t]=a[s];
        float qs=bsum(a[s],red);
        if(t==0) g_qksum[b*8+s]=qs;
    }
}

// grid (32 tiles, 128 batches), 128 threads, dyn smem
__global__ void __launch_bounds__(128) k_attn(const float* __restrict__ inputs){
    extern __shared__ float sm[];
    float* XS = sm;               // 128*132
    float* QK = XS + 128*132;     // 8*128
    float* AA = QK + 1024;        // 128*8
    float* QS = AA + 1024;        // 8
    float* CW = QS + 8;           // 32
    float* CB = CW + 32;          // 32
    float* PART = CB + 32;        // 4*8*128
    const int t=threadIdx.x, lane=t&31, w=t>>5;
    const int tile=blockIdx.x, b=blockIdx.y;

    { const float4* gsrc=(const float4*)(inputs + ((size_t)b*4096 + tile*128)*128);
      #pragma unroll 8
      for(int j=t;j<4096;j+=128){ int r=j>>5,c=j&31; *(float4*)(XS+r*132+c*4)=gsrc[j]; } }
    { int s=t>>4, i=(t&15)*8;
      const float4* q=(const float4*)(g_qk+(b*8+s)*128+i);
      *(float4*)(QK+s*128+i)=q[0]; *(float4*)(QK+s*128+i+4)=q[1];
      if(t<8) QS[t]=g_qksum[b*8+t]; }
    __syncthreads();

    // phase 2: thread t owns row t
    float at[8], mu;
    {
        ull pd[8]; ull s1=0ull,s2=0ull;
        #pragma unroll
        for(int s=0;s<8;s++) pd[s]=0ull;
        const ulonglong2* xp=(const ulonglong2*)(XS+t*132);
        #pragma unroll 2
        for(int c=0;c<32;c++){
            ulonglong2 xv=xp[c];
            s1=add2(s1,xv.x); s1=add2(s1,xv.y);
            s2=fma2(xv.x,xv.x,s2); s2=fma2(xv.y,xv.y,s2);
            #pragma unroll
            for(int s=0;s<8;s++){
                ulonglong2 qv=((const ulonglong2*)(QK+s*128))[c];
                pd[s]=fma2(xv.x,qv.x,pd[s]); pd[s]=fma2(xv.y,qv.y,pd[s]);
            }
        }
        float a,bq; unpk(s1,a,bq); float sum=a+bq;
        unpk(s2,a,bq); float sumsq=a+bq;
        mu = sum*(1.f/128.f);
        float var = sumsq*(1.f/128.f)-mu*mu;
        float rstd = rsqrtf(var+LN_EPS);
        float lg[8];
        #pragma unroll
        for(int s=0;s<8;s++){ unpk(pd[s],a,bq); lg[s]=SCALE*rstd*((a+bq)-mu*QS[s]); }
        float m=lg[0];
        #pragma unroll
        for(int s=1;s<8;s++) m=fmaxf(m,lg[s]);
        float e[8], tot=0.f;
        #pragma unroll
        for(int s=0;s<8;s++){ e[s]=__expf(lg[s]-m); tot+=e[s]; }
        float inv=1.f/tot;
        #pragma unroll
        for(int s=0;s<8;s++){ at[s]=e[s]*inv+EPS_ATTN; AA[t*8+s]=at[s]*rstd; }
    }
    // warp-level colsum / csub partials
    #pragma unroll
    for(int s=0;s<8;s++){
        float v=at[s];
        #pragma unroll
        for(int o=16;o>0;o>>=1) v+=__shfl_xor_sync(0xffffffffu,v,o);
        float u=at[s]*mu; // *rstd applied below via av? csub = sum(av*mu) = sum(at*rstd*mu)
        u=AA[t*8+s]*mu;
        #pragma unroll
        for(int o=16;o>0;o>>=1) u+=__shfl_xor_sync(0xffffffffu,u,o);
        if(lane==0){ CW[w*8+s]=v; CB[w*8+s]=u; }
    }
    __syncthreads();

    // phase 3: warp w -> rows [w*32, w*32+32), lane -> cols lane*4..+3
    ull acc[8][2];
    #pragma unroll
    for(int s=0;s<8;s++){ acc[s][0]=0ull; acc[s][1]=0ull; }
    for(int r0=0;r0<32;r0++){
        int r=w*32+r0;
        ulonglong2 xv=*(const ulonglong2*)(XS + r*132 + lane*4);
        const float* a8=AA+r*8;
        float4 alo=*(const float4*)a8, ahi=*(const float4*)(a8+4);
        acc[0][0]=fma2(pk2(alo.x,alo.x),xv.x,acc[0][0]); acc[0][1]=fma2(pk2(alo.x,alo.x),xv.y,acc[0][1]);
        acc[1][0]=fma2(pk2(alo.y,alo.y),xv.x,acc[1][0]); acc[1][1]=fma2(pk2(alo.y,alo.y),xv.y,acc[1][1]);
        acc[2][0]=fma2(pk2(alo.z,alo.z),xv.x,acc[2][0]); acc[2][1]=fma2(pk2(alo.z,alo.z),xv.y,acc[2][1]);
        acc[3][0]=fma2(pk2(alo.w,alo.w),xv.x,acc[3][0]); acc[3][1]=fma2(pk2(alo.w,alo.w),xv.y,acc[3][1]);
        acc[4][0]=fma2(pk2(ahi.x,ahi.x),xv.x,acc[4][0]); acc[4][1]=fma2(pk2(ahi.x,ahi.x),xv.y,acc[4][1]);
        acc[5][0]=fma2(pk2(ahi.y,ahi.y),xv.x,acc[5][0]); acc[5][1]=fma2(pk2(ahi.y,ahi.y),xv.y,acc[5][1]);
        acc[6][0]=fma2(pk2(ahi.z,ahi.z),xv.x,acc[6][0]); acc[6][1]=fma2(pk2(ahi.z,ahi.z),xv.y,acc[6][1]);
        acc[7][0]=fma2(pk2(ahi.w,ahi.w),xv.x,acc[7][0]); acc[7][1]=fma2(pk2(ahi.w,ahi.w),xv.y,acc[7][1]);
    }
    if(t<8){
        g_cs[(b*32+tile)*8+t]=CW[t]+CW[8+t]+CW[16+t]+CW[24+t];
        g_cb[(b*32+tile)*8+t]=CB[t]+CB[8+t]+CB[16+t]+CB[24+t];
    }
    #pragma unroll
    for(int s=0;s<8;s++)
        *(ulonglong2*)(PART+(w*8+s)*128+lane*4)=make_ulonglong2(acc[s][0],acc[s][1]);
    __syncthreads();
    {
        int s=t>>4, c0=(t&15)*8;
        float o[8];
        #pragma unroll
        for(int j=0;j<8;j++)
            o[j]=PART[s*128+c0+j]+PART[(8+s)*128+c0+j]+PART[(16+s)*128+c0+j]+PART[(24+s)*128+c0+j];
        float* dst=g_part+(((size_t)(b*32+tile)*8+s)*128+c0);
        *(float4*)dst=make_float4(o[0],o[1],o[2],o[3]);
        *(float4*)(dst+4)=make_float4(o[4],o[5],o[6],o[7]);
    }
}

// block = batch: T, updates=T@Wv.T, GRU, MLP -> slots (+out)
__global__ void __launch_bounds__(128) k_update(
    const float* __restrict__ Wv, const float* __restrict__ W_ih, const float* __restrict__ W_hh,
    const float* __restrict__ b_ih, const float* __restrict__ b_hh,
    const float* __restrict__ W1, const float* __restrict__ b1,
    const float* __restrict__ W2, const float* __restrict__ b2, float* __restrict__ out)
{
    __shared__ float Ts[8][128], Us[8][128], Hs[8][128], H1s[8][256], CS[8], CBs[8], red[4];
    int b=blockIdx.x, t=threadIdx.x;
    if(t<8){
        float cs=0.f,cb=0.f;
        for(int k=0;k<32;k++){ cs+=g_cs[(b*32+k)*8+t]; cb+=g_cb[(b*32+k)*8+t]; }
        CS[t]=1.f/cs; CBs[t]=cb;
    }
    __syncthreads();
    #pragma unroll
    for(int s=0;s<8;s++){
        float a=0.f;
        const float* p=g_part+((size_t)(b*32)*8+s)*128+t;
        #pragma unroll 8
        for(int k=0;k<32;k++) a+=p[(size_t)k*1024];
        Ts[s][t]=(a-CBs[s])*CS[s];
        Hs[s][t]=g_slots_n[(b*8+s)*128+t];
    }
    __syncthreads();
    float u[8]={0,0,0,0,0,0,0,0};
    { const float4* wv=(const float4*)(Wv+(size_t)t*128);
      #pragma unroll 4
      for(int c=0;c<32;c++){ float4 wc=wv[c];
        #pragma unroll
        for(int s=0;s<8;s++) u[s]+=dot4(wc,((const float4*)Ts[s])[c]); } }
    #pragma unroll
    for(int s=0;s<8;s++) Us[s][t]=u[s];
    __syncthreads();

    float xr[8],xz[8],xn[8];
    #pragma unroll
    for(int s=0;s<8;s++){ xr[s]=b_ih[t]; xz[s]=b_ih[t+128]; xn[s]=b_ih[t+256]; }
    { const float4* w0=(const float4*)(W_ih+(size_t)t*128);
      const float4* w1p=(const float4*)(W_ih+(size_t)(t+128)*128);
      const float4* w2p=(const float4*)(W_ih+(size_t)(t+256)*128);
      for(int c=0;c<32;c++){ float4 a0=w0[c],a1=w1p[c],a2=w2p[c];
        #pragma unroll
        for(int s=0;s<8;s++){ float4 uu=((const float4*)Us[s])[c];
          xr[s]+=dot4(a0,uu); xz[s]+=dot4(a1,uu); xn[s]+=dot4(a2,uu); } } }
    float hr[8],hz[8],hn[8];
    #pragma unroll
    for(int s=0;s<8;s++){ hr[s]=b_hh[t]; hz[s]=b_hh[t+128]; hn[s]=b_hh[t+256]; }
    { const float4* w0=(const float4*)(W_hh+(size_t)t*128);
      const float4* w1p=(const float4*)(W_hh+(size_t)(t+128)*128);
      const float4* w2p=(const float4*)(W_hh+(size_t)(t+256)*128);
      for(int c=0;c<32;c++){ float4 a0=w0[c],a1=w1p[c],a2=w2p[c];
        #pragma unroll
        for(int s=0;s<8;s++){ float4 hh=((const float4*)Hs[s])[c];
          hr[s]+=dot4(a0,hh); hz[s]+=dot4(a1,hh); hn[s]+=dot4(a2,hh); } } }
    float sd[8];
    #pragma unroll
    for(int s=0;s<8;s++){
        float r=1.f/(1.f+__expf(-(xr[s]+hr[s])));
        float z=1.f/(1.f+__expf(-(xz[s]+hz[s])));
        float n=tanhf(xn[s]+r*hn[s]);
        sd[s]=(1.f-z)*n+z*Hs[s][t];
    }
    // MLP: LN(sd) -> Ts (reuse)
    #pragma unroll
    for(int s=0;s<8;s++){
        float m=bsum(sd[s],red)*(1.f/128.f);
        float dv=sd[s]-m;
        float var=bsum(dv*dv,red)*(1.f/128.f);
        Ts[s][t]=dv*rsqrtf(var+LN_EPS);
    }
    __syncthreads();
    #pragma unroll
    for(int j2=0;j2<2;j2++){
        int j=t+j2*128;
        float h[8];
        #pragma unroll
        for(int s=0;s<8;s++) h[s]=b1[j];
        const float4* w1=(const float4*)(W1+(size_t)j*128);
        for(int c=0;c<32;c++){ float4 wc=w1[c];
            #pragma unroll
            for(int s=0;s<8;s++) h[s]+=dot4(wc,((const float4*)Ts[s])[c]); }
        #pragma unroll
        for(int s=0;s<8;s++) H1s[s][j]=fmaxf(h[s],0.f);
    }
    __syncthreads();
    float o[8];
    #pragma unroll
    for(int s=0;s<8;s++) o[s]=sd[s]+b2[t];
    { const float4* w2=(const float4*)(W2+(size_t)t*256);
      for(int c=0;c<64;c++){ float4 wc=w2[c];
        #pragma unroll
        for(int s=0;s<8;s++) o[s]+=dot4(wc,((const float4*)H1s[s])[c]); } }
    #pragma unroll
    for(int s=0;s<8;s++){
        g_slots[(b*8+s)*128+t]=o[s];
        out[(b*8+s)*128+t]=o[s];
    }
}

#define ATTN_SMEM_BYTES (23112*4)

extern "C" void kernel_launch(void* const* d_in, const int* in_sizes, int n_in,
                              void* d_out, int out_size){
    const float* inputs=(const float*)d_in[0];
    const float* noise =(const float*)d_in[1];
    const float* smu   =(const float*)d_in[2];
    const float* sls   =(const float*)d_in[3];
    const float* Wq    =(const float*)d_in[4];
    const float* Wk    =(const float*)d_in[5];
    const float* Wv    =(const float*)d_in[6];
    const float* W_ih  =(const float*)d_in[7];
    const float* W_hh  =(const float*)d_in[8];
    const float* b_ih  =(const float*)d_in[9];
    const float* b_hh  =(const float*)d_in[10];
    const float* W1    =(const float*)d_in[11];
    const float* b1    =(const float*)d_in[12];
    const float* W2    =(const float*)d_in[13];
    const float* b2    =(const float*)d_in[14];
    float* out=(float*)d_out;

    cudaFuncSetAttribute(k_attn, cudaFuncAttributeMaxDynamicSharedMemorySize, ATTN_SMEM_BYTES);

    k_init<<<512,256>>>(noise,smu,sls);
    for(int it=0; it<3; it++){
        k_project<<<128,128>>>(Wq,Wk);
        dim3 g(32,128);
        k_attn<<<g,128,ATTN_SMEM_BYTES>>>(inputs);
        k_update<<<128,128>>>(Wv,W_ih,W_hh,b_ih,b_hh,W1,b1,W2,b2,out);
    }
}